// round 17
// baseline (speedup 1.0000x reference)
#include <cuda_runtime.h>
#include <cuda.h>
#include <cuda_fp16.h>
#include <cstdint>

// Vanilla tanh RNN: h_t = tanh(x_t W_ih^T + b_ih + h_{t-1} W_hh^T + b_hh)
// B=4096, T=256, I=H=64. Output: [hT (B*H) | all h_t (B*T*H)] fp32.
//
// 2x2 WARP TILING, RPB=32: 128 blocks x 128 threads (1 CTA/SM). Warp (mh,nh)
// owns rows mh*16..+15 x cols nh*32..+31 -> each 16-row A-tile half is read
// by only 2 warps (amplification 4x -> 2x vs R10; per-SM smem traffic
// 78 -> 56 KB/step per 32 rows). 32 MMA/warp/step (4 n-tiles x 4 kt x 2
// GEMMs). TMA x loads (32,32,4) fp32 chunks double-buffered; fp32->fp16
// convert once per step; out staged in swizzled fp32 tiles (double
// buffered) and TMA-stored per chunk. One __syncthreads per step.

constexpr int Bsz = 4096, T = 256, H = 64;
constexpr int RPB = 32, GRID = Bsz / RPB;     // 128 blocks
constexpr int CH = 4, NCH = T / CH;           // 64 chunks
constexpr int NT = 128;                       // 4 warps (2m x 2n)
// smem byte offsets (SM_O 1024-aligned — required by SW128 TMA store phase)
constexpr int SM_X32 = 0;        // [2][32768] fp32 x staging (TMA, SW128)
constexpr int SM_X16 = 65536;    // [2][4 step][32 rows * 144B] fp16 x tiles
constexpr int SM_H   = 102400;   // [2][32 * 144B] fp16 h tiles
constexpr int SM_O   = 111616;   // [2][32768] fp32 out staging (SW128)
constexpr int SM_MB  = 177152;   // 2 mbarriers
constexpr int SMEM_TOTAL = 177168;

__device__ __forceinline__ uint32_t packh2(float a, float b) {
    __half2 h = __floats2half2_rn(a, b);
    return *reinterpret_cast<uint32_t*>(&h);
}

__device__ __forceinline__ void mma16(float* c, const uint32_t* a, const uint32_t* b) {
    asm volatile(
        "mma.sync.aligned.m16n8k16.row.col.f32.f16.f16.f32 "
        "{%0,%1,%2,%3}, {%4,%5,%6,%7}, {%8,%9}, {%0,%1,%2,%3};"
        : "+f"(c[0]), "+f"(c[1]), "+f"(c[2]), "+f"(c[3])
        : "r"(a[0]), "r"(a[1]), "r"(a[2]), "r"(a[3]), "r"(b[0]), "r"(b[1]));
}

__device__ __forceinline__ void ldsm4(uint32_t* a, uint32_t addr) {
    asm volatile("ldmatrix.sync.aligned.m8n8.x4.shared.b16 {%0,%1,%2,%3}, [%4];"
                 : "=r"(a[0]), "=r"(a[1]), "=r"(a[2]), "=r"(a[3])
                 : "r"(addr));
}

__device__ __forceinline__ float tanh_mufu(float z) {
    float r;
    asm("tanh.approx.f32 %0, %1;" : "=f"(r) : "f"(z));
    return r;
}

__device__ __forceinline__ void tma_load3d(uint32_t sdst, const CUtensorMap* m,
                                           int cx, int cy, int cz, uint32_t mbar) {
    asm volatile(
        "cp.async.bulk.tensor.3d.shared::cta.global.tile.mbarrier::complete_tx::bytes "
        "[%0], [%1, {%2, %3, %4}], [%5];"
        :: "r"(sdst), "l"(m), "r"(cx), "r"(cy), "r"(cz), "r"(mbar) : "memory");
}

__device__ __forceinline__ void tma_store3d(const CUtensorMap* m,
                                            int cx, int cy, int cz, uint32_t ssrc) {
    asm volatile(
        "cp.async.bulk.tensor.3d.global.shared::cta.tile.bulk_group "
        "[%0, {%1, %2, %3}], [%4];"
        :: "l"(m), "r"(cx), "r"(cy), "r"(cz), "r"(ssrc) : "memory");
}

__device__ __forceinline__ void mbar_wait(uint32_t mbar, int parity) {
    asm volatile(
        "{\n\t.reg .pred P;\n\t"
        "W%=:\n\t"
        "mbarrier.try_wait.parity.acquire.cta.shared::cta.b64 P, [%0], %1, 0x989680;\n\t"
        "@!P bra W%=;\n\t}"
        :: "r"(mbar), "r"(parity) : "memory");
}

__global__ void __launch_bounds__(NT, 1)
rnn_fused(const __grid_constant__ CUtensorMap xmap,
          const __grid_constant__ CUtensorMap omap,
          const float* __restrict__ h0,
          const float* __restrict__ Wih, const float* __restrict__ Whh,
          const float* __restrict__ bih, const float* __restrict__ bhh,
          float* __restrict__ dout)
{
    extern __shared__ __align__(1024) char smem[];
    const uint32_t sb = (uint32_t)__cvta_generic_to_shared(smem);
    const uint32_t mbA[2] = {sb + SM_MB, sb + SM_MB + 8};

    const int tid  = threadIdx.x;
    const int lane = tid & 31;
    const int q    = tid >> 5;          // warp id
    const int mh   = q >> 1;            // m-half: rows mh*16..+15
    const int nh   = q & 1;             // n-half: cols nh*32..+31
    const int gid  = lane >> 2;
    const int tig  = lane & 3;
    const int b0   = blockIdx.x * RPB;
    const int row0 = b0 + mh * 16 + gid;

    // ---- TMA prologue: mbars + chunks 0,1 (32KB each, two 16KB halves) ----
    if (tid == 0) {
        asm volatile("mbarrier.init.shared.b64 [%0], 1;" :: "r"(mbA[0]));
        asm volatile("mbarrier.init.shared.b64 [%0], 1;" :: "r"(mbA[1]));
        asm volatile("fence.proxy.async.shared::cta;" ::: "memory");
        asm volatile("mbarrier.arrive.expect_tx.shared.b64 _, [%0], %1;"
                     :: "r"(mbA[0]), "r"(32768));
        tma_load3d(sb + SM_X32,         &xmap, 0,  b0, 0, mbA[0]);
        tma_load3d(sb + SM_X32 + 16384, &xmap, 32, b0, 0, mbA[0]);
        asm volatile("mbarrier.arrive.expect_tx.shared.b64 _, [%0], %1;"
                     :: "r"(mbA[1]), "r"(32768));
        tma_load3d(sb + SM_X32 + 32768,         &xmap, 0,  b0, CH, mbA[1]);
        tma_load3d(sb + SM_X32 + 32768 + 16384, &xmap, 32, b0, CH, mbA[1]);
    }
    __syncthreads();   // mbar init visible to all before any wait

    // ---- weights for this warp's 32 cols (4 n-tiles) ----
    uint32_t wih[4][4][2], whh[4][4][2];
    float bias[4][2];
    #pragma unroll
    for (int nt = 0; nt < 4; ++nt) {
        const int n = nh * 32 + nt * 8 + gid;
        #pragma unroll
        for (int kt = 0; kt < 4; ++kt) {
            const int k = kt * 16 + 2 * tig;
            wih[nt][kt][0] = packh2(Wih[n * H + k],     Wih[n * H + k + 1]);
            wih[nt][kt][1] = packh2(Wih[n * H + k + 8], Wih[n * H + k + 9]);
            whh[nt][kt][0] = packh2(Whh[n * H + k],     Whh[n * H + k + 1]);
            whh[nt][kt][1] = packh2(Whh[n * H + k + 8], Whh[n * H + k + 9]);
        }
        const int col = nh * 32 + nt * 8 + 2 * tig;
        bias[nt][0] = bih[col]     + bhh[col];
        bias[nt][1] = bih[col + 1] + bhh[col + 1];
    }

    // ---- h0 -> hbuf[0] (padded fp16 tile, 144B rows, 32 rows) ----
    #pragma unroll
    for (int j = 0; j < 2; ++j) {
        const int idx = tid * 2 + j;        // 0..255
        const int r = idx >> 3, g8 = idx & 7;
        const float* hp = h0 + (size_t)(b0 + r) * H + g8 * 8;
        float4 a = *(const float4*)hp, b2 = *(const float4*)(hp + 4);
        *(uint4*)(smem + SM_H + r * 144 + g8 * 16) =
            make_uint4(packh2(a.x, a.y), packh2(a.z, a.w),
                       packh2(b2.x, b2.y), packh2(b2.z, b2.w));
    }

    // ---- fp32->fp16 x conversion: thread covers row cr, 16 float cols ----
    const int cr = tid >> 2, cgq = tid & 3;
    auto convert = [&](int buf, int step) {
        #pragma unroll
        for (int j = 0; j < 2; ++j) {
            const int c0 = cgq * 16 + j * 8;      // float col base (8 floats)
            const int ch = c0 >> 5;
            const char* src = smem + SM_X32 + buf * 32768 + ch * 16384
                            + step * 4096 + cr * 128;
            const uint32_t o = (uint32_t)((c0 & 31) * 4);
            const uint32_t k = (uint32_t)((cr & 7) << 4);
            float4 a  = *(const float4*)(src + ((o)      ^ k));
            float4 b2 = *(const float4*)(src + ((o + 16) ^ k));
            *(uint4*)(smem + SM_X16 + buf * 18432 + step * 4608
                      + cr * 144 + c0 * 2) =
                make_uint4(packh2(a.x, a.y), packh2(a.z, a.w),
                           packh2(b2.x, b2.y), packh2(b2.z, b2.w));
        }
    };

    // ldmatrix lane offset within this warp's 16-row half of a 32x64h tile
    const int mat = lane >> 3, mr = lane & 7;
    const uint32_t aoff =
        (uint32_t)((mh * 16 + (mat & 1) * 8 + mr) * 144 + (mat >> 1) * 16);
    const uint32_t x16b = sb + SM_X16;
    const uint32_t hbB  = sb + SM_H;

    // ---- prologue: wait chunk0, convert it, initial acc = bias + xW(0) ----
    mbar_wait(mbA[0], 0);
    #pragma unroll
    for (int s = 0; s < CH; ++s) convert(0, s);
    __syncthreads();

    float acc[4][4];
    #pragma unroll
    for (int nt = 0; nt < 4; ++nt) {
        acc[nt][0] = bias[nt][0]; acc[nt][1] = bias[nt][1];
        acc[nt][2] = bias[nt][0]; acc[nt][3] = bias[nt][1];
    }
    #pragma unroll
    for (int kt = 0; kt < 4; ++kt) {
        uint32_t a[4];
        ldsm4(a, x16b + aoff + kt * 32);
        #pragma unroll
        for (int nt = 0; nt < 4; ++nt) mma16(acc[nt], a, wih[nt][kt]);
    }

    int ph[2] = {1, 0};   // next parities for mb0/mb1

    for (int t = 0; t < T; ++t) {
        const int tl = t & 3, c = t >> 2, cb = c & 1, nb = cb ^ 1, pb = t & 1;

        // ---- chunk-start TMA bookkeeping (store c-1, load c+2) ----
        if (tl == 0 && tid == 0) {
            if (c > 0) {
                asm volatile("fence.proxy.async.shared::cta;" ::: "memory");
                const int pc = c - 1;
                const uint32_t osrc = sb + SM_O + (pc & 1) * 32768;
                tma_store3d(&omap, 0,  b0, pc * CH, osrc);
                tma_store3d(&omap, 32, b0, pc * CH, osrc + 16384);
                asm volatile("cp.async.bulk.commit_group;" ::: "memory");
            }
            if (c + 2 < NCH) {
                asm volatile("mbarrier.arrive.expect_tx.shared.b64 _, [%0], %1;"
                             :: "r"(mbA[cb]), "r"(32768));
                tma_load3d(sb + SM_X32 + cb * 32768,         &xmap, 0,  b0, (c + 2) * CH, mbA[cb]);
                tma_load3d(sb + SM_X32 + cb * 32768 + 16384, &xmap, 32, b0, (c + 2) * CH, mbA[cb]);
            }
            if (c > 0)
                asm volatile("cp.async.bulk.wait_group.read 1;" ::: "memory");
        }
        if (tl == 0 && c + 1 < NCH) { mbar_wait(mbA[nb], ph[nb]); ph[nb] ^= 1; }

        // ---- h-GEMM: acc += h_{t-1} @ W_hh^T (ldmatrix from hbuf[pb]) ----
        {
            const uint32_t hrd = hbB + pb * 4608 + aoff;
            #pragma unroll
            for (int kt = 0; kt < 4; ++kt) {
                uint32_t a[4];
                ldsm4(a, hrd + kt * 32);
                #pragma unroll
                for (int nt = 0; nt < 4; ++nt) mma16(acc[nt], a, whh[nt][kt]);
            }
        }

        // ---- tanh -> publish h (STS) + out staging (STS, swizzled) ----
        {
            uint32_t* hw = (uint32_t*)(smem + SM_H + (pb ^ 1) * 4608);
            char* otile = smem + SM_O + (c & 1) * 32768 + nh * 16384 + tl * 4096;
            const uint32_t k2 = (uint32_t)(gid << 4);
            const int rbase = (mh * 16 + gid) * 36;
            #pragma unroll
            for (int nt = 0; nt < 4; ++nt) {
                const float v0 = tanh_mufu(acc[nt][0]);
                const float v1 = tanh_mufu(acc[nt][1]);
                const float v2 = tanh_mufu(acc[nt][2]);
                const float v3 = tanh_mufu(acc[nt][3]);
                hw[rbase + nh * 16 + nt * 4 + tig]           = packh2(v0, v1);
                hw[rbase + 8 * 36 + nh * 16 + nt * 4 + tig]  = packh2(v2, v3);
                const uint32_t co = (uint32_t)((nt * 8 + 2 * tig) * 4);
                const uint32_t ro = (uint32_t)((mh * 16 + gid) * 128);
                *(float2*)(otile + ((ro + co) ^ k2))                = make_float2(v0, v1);
                *(float2*)(otile + ((ro + 8 * 128 + co) ^ k2))      = make_float2(v2, v3);
                if (t == T - 1) {
                    const int col = nh * 32 + nt * 8 + 2 * tig;
                    *(float2*)(dout + (size_t)row0 * H + col)       = make_float2(v0, v1);
                    *(float2*)(dout + (size_t)(row0 + 8) * H + col) = make_float2(v2, v3);
                }
                acc[nt][0] = bias[nt][0]; acc[nt][1] = bias[nt][1];
                acc[nt][2] = bias[nt][0]; acc[nt][3] = bias[nt][1];
            }
        }

        // ---- x-GEMM for t+1 (independent of the h chain) ----
        if (t + 1 < T) {
            const uint32_t xrd = x16b +
                ((tl < 3) ? (uint32_t)(cb * 18432 + (tl + 1) * 4608)
                          : (uint32_t)(nb * 18432)) + aoff;
            #pragma unroll
            for (int kt = 0; kt < 4; ++kt) {
                uint32_t a[4];
                ldsm4(a, xrd + kt * 32);
                #pragma unroll
                for (int nt = 0; nt < 4; ++nt) mma16(acc[nt], a, wih[nt][kt]);
            }
        }

        // ---- convert step tl of next chunk (off-chain) ----
        if (c + 1 < NCH) convert(nb, tl);

        __syncthreads();
    }

    // ---- final chunk store ----
    if (tid == 0) {
        asm volatile("fence.proxy.async.shared::cta;" ::: "memory");
        const int pc = NCH - 1;
        const uint32_t osrc = sb + SM_O + (pc & 1) * 32768;
        tma_store3d(&omap, 0,  b0, pc * CH, osrc);
        tma_store3d(&omap, 32, b0, pc * CH, osrc + 16384);
        asm volatile("cp.async.bulk.commit_group;" ::: "memory");
        asm volatile("cp.async.bulk.wait_group 0;" ::: "memory");
    }
}

typedef CUresult (*tmap_encode_fn)(
    CUtensorMap*, CUtensorMapDataType, cuuint32_t, void*,
    const cuuint64_t*, const cuuint64_t*, const cuuint32_t*, const cuuint32_t*,
    CUtensorMapInterleave, CUtensorMapSwizzle, CUtensorMapL2promotion,
    CUtensorMapFloatOOBfill);

extern "C" void kernel_launch(void* const* d_in, const int* in_sizes, int n_in,
                              void* d_out, int out_size) {
    const float* x   = (const float*)d_in[0];
    const float* h0  = (const float*)d_in[1];
    const float* Wih = (const float*)d_in[2];
    const float* Whh = (const float*)d_in[3];
    const float* bih = (const float*)d_in[4];
    const float* bhh = (const float*)d_in[5];
    float* dout = (float*)d_out;
    (void)in_sizes; (void)n_in; (void)out_size;

    void* fn = nullptr;
    cudaDriverEntryPointQueryResult qr;
    cudaGetDriverEntryPointByVersion("cuTensorMapEncodeTiled", &fn, 12000,
                                     cudaEnableDefault, &qr);
    tmap_encode_fn enc = (tmap_encode_fn)fn;

    // x and out are [B, T, 64] fp32; dims (h, b, t); box (32, 32, 4), SW128.
    cuuint64_t gdim[3] = {64, (cuuint64_t)Bsz, (cuuint64_t)T};
    cuuint64_t gstr[2] = {(cuuint64_t)T * H * sizeof(float),
                          (cuuint64_t)H * sizeof(float)};
    cuuint32_t box[3]  = {32, RPB, CH};
    cuuint32_t estr[3] = {1, 1, 1};

    CUtensorMap xmap, omap;
    enc(&xmap, CU_TENSOR_MAP_DATA_TYPE_FLOAT32, 3, (void*)x,
        gdim, gstr, box, estr, CU_TENSOR_MAP_INTERLEAVE_NONE,
        CU_TENSOR_MAP_SWIZZLE_128B, CU_TENSOR_MAP_L2_PROMOTION_L2_128B,
        CU_TENSOR_MAP_FLOAT_OOB_FILL_NONE);
    enc(&omap, CU_TENSOR_MAP_DATA_TYPE_FLOAT32, 3, (void*)(dout + (size_t)Bsz * H),
        gdim, gstr, box, estr, CU_TENSOR_MAP_INTERLEAVE_NONE,
        CU_TENSOR_MAP_SWIZZLE_128B, CU_TENSOR_MAP_L2_PROMOTION_L2_128B,
        CU_TENSOR_MAP_FLOAT_OOB_FILL_NONE);

    cudaFuncSetAttribute(rnn_fused, cudaFuncAttributeMaxDynamicSharedMemorySize,
                         SMEM_TOTAL);
    rnn_fused<<<GRID, NT, SMEM_TOTAL>>>(xmap, omap, h0, Wih, Whh, bih, bhh, dout);
}